// round 15
// baseline (speedup 1.0000x reference)
#include <cuda_runtime.h>
#include <cstdint>

#define NS 25
#define NC 80
#define CD 6400
#define BT 25600

#define MTB 128
#define NTB 128
#define THREADS 256
#define NXB 50
#define NYB 8
#define MTILES 200
#define NMB 16

#define PL 16
#define PSTR 132

// dynamic smem (bytes): BHL | stage
#define OFF_BHL   0
#define OFF_STAGE (PL * PSTR * 8)          // 16896
#define SMB       (OFF_STAGE + 8 * 512 * 8) // 49664

// Pre-split A fragments: [tile][rowg][lane][16] uint2  (3.28 MB)
__device__ uint2 ascr[MTILES * 4 * 32 * 16];

__device__ __forceinline__ uint16_t f2bf(float v) {
    uint16_t r;
    asm("cvt.rn.bf16.f32 %0, %1;" : "=h"(r) : "f"(v));
    return r;
}
__device__ __forceinline__ float bf2f(uint16_t h) {
    return __uint_as_float((uint32_t)h << 16);
}
__device__ __forceinline__ void mma_bf16(float* acc, const uint32_t* a,
                                         uint32_t b0, uint32_t b1) {
    asm volatile(
        "mma.sync.aligned.m16n8k16.row.col.f32.bf16.bf16.f32 "
        "{%0,%1,%2,%3}, {%4,%5,%6,%7}, {%8,%9}, {%0,%1,%2,%3};"
        : "+f"(acc[0]), "+f"(acc[1]), "+f"(acc[2]), "+f"(acc[3])
        : "r"(a[0]), "r"(a[1]), "r"(a[2]), "r"(a[3]), "r"(b0), "r"(b1));
}
__device__ __forceinline__ int pidx(int plane, int x) {
    return plane * PSTR + (x ^ ((plane & 3) << 3));
}
__device__ __forceinline__ float softplus_f(float x) { return log1pf(expf(x)); }

// ---------------------------------------------------------------------------
// Prep: split A (softplus-scaled) into bf16 hi/lo k-pair fragments, laid out
// exactly in the main kernel's per-lane register order.
// ---------------------------------------------------------------------------
__global__ __launch_bounds__(256)
void prep_kernel(const float* __restrict__ alpha,
                 const float* __restrict__ asc)
{
    __shared__ float sc[32];
    const int tid = threadIdx.x;
    if (tid < 32) sc[tid] = (tid < NS) ? softplus_f(asc[tid]) : 0.f;
    __syncthreads();

    const int row = blockIdx.x * 256 + tid;          // 0..25599
    const float* ap = alpha + (size_t)row * NS;

    float a[26];
    #pragma unroll
    for (int k = 0; k < NS; k++) a[k] = ap[k] * sc[k];
    a[25] = 0.f;

    const int tile  = row >> 7;
    const int rowg  = (row >> 5) & 3;
    const int row32 = row & 31;
    const int m     = row32 >> 4;
    const int rem   = row32 & 15;
    const int b     = rem >> 3;
    const int grp   = rem & 7;

    uint2* base = ascr + (size_t)(tile * 4 + rowg) * 32 * 16;
    #pragma unroll
    for (int kp = 0; kp < 16; kp++) {
        const float v0 = (kp < 13) ? a[2 * kp] : 0.f;
        const float v1 = (kp < 13) ? a[2 * kp + 1] : 0.f;
        const uint16_t h0 = f2bf(v0), h1 = f2bf(v1);
        const uint16_t l0 = f2bf(v0 - bf2f(h0)), l1 = f2bf(v1 - bf2f(h1));
        const int kk = kp & 3, g = kp >> 3, c = (kp >> 2) & 1;
        const int lane = grp * 4 + kk;
        const int f = m * 8 + g * 4 + c * 2 + b;
        base[lane * 16 + f] = make_uint2((uint32_t)h0 | ((uint32_t)h1 << 16),
                                         (uint32_t)l0 | ((uint32_t)l1 << 16));
    }
}

// ---------------------------------------------------------------------------
// Main fused kernel: C stripes (bx<50) + m blocks (bx>=50).
// C path has NO barriers in the tile loop: frags via coalesced LDG.128.
// ---------------------------------------------------------------------------
__global__ __launch_bounds__(THREADS, 3)
void fused_kernel(const float* __restrict__ alpha,
                  const float* __restrict__ mu,
                  const float* __restrict__ D,
                  const float* __restrict__ asc,
                  float* __restrict__ m_out,
                  float* __restrict__ C)
{
    extern __shared__ char dsm[];
    const int tid = threadIdx.x;
    const int bx = blockIdx.x, by = blockIdx.y;

    if (bx >= NXB) {
        // =================== m path ===================
        float* mu_s = reinterpret_cast<float*>(dsm);
        float* a_s  = mu_s + 2048;
        float* sc   = a_s + 3232;

        if (tid < NS) sc[tid] = softplus_f(asc[tid]);
        for (int i = tid; i < NS * NC; i += THREADS) mu_s[i] = mu[i];
        __syncthreads();

        const int active = (tid < 160);
        const int c = tid % 80, h = tid / 80;
        float mur[NS];
        if (active) {
            #pragma unroll
            for (int j = 0; j < NS; j++) mur[j] = mu_s[j * NC + c];
        }

        const int mid = (bx - NXB) + 2 * by;
        for (int mt = mid; mt < MTILES; mt += NMB) {
            const int bt0 = mt * MTB;
            __syncthreads();
            const float* ap = alpha + (size_t)bt0 * NS;
            for (int i = tid; i < MTB * NS; i += THREADS) {
                const int j = i % NS;
                a_s[i] = ap[i] * sc[j];
            }
            __syncthreads();
            if (active) {
                #pragma unroll 4
                for (int rr = 0; rr < 64; rr++) {
                    const int r = h * 64 + rr;
                    float s = 0.f;
                    #pragma unroll
                    for (int j = 0; j < NS; j++) s = fmaf(a_s[r * NS + j], mur[j], s);
                    __stcs(&m_out[(size_t)(bt0 + r) * NC + c], s);
                }
            }
        }
        return;
    }

    // =================== C path ===================
    uint2*  BHL   = reinterpret_cast<uint2*>(dsm + OFF_BHL);
    float2* stage = reinterpret_cast<float2*>(dsm + OFF_STAGE);

    // zero pad planes 13..15
    for (int i = tid; i < 3 * PSTR; i += THREADS)
        BHL[13 * PSTR + i] = make_uint2(0, 0);

    const int nb = bx * NTB;

    // B split (once): packed k-pairs, swizzled
    for (int it = tid; it < 13 * NTB; it += THREADS) {
        const int kp = it >> 7, n = it & 127;
        const float v0 = D[(size_t)(2 * kp) * CD + nb + n];
        const float v1 = (kp < 12) ? D[(size_t)(2 * kp + 1) * CD + nb + n] : 0.f;
        const uint16_t h0 = f2bf(v0), h1 = f2bf(v1);
        const uint16_t l0 = f2bf(v0 - bf2f(h0)), l1 = f2bf(v1 - bf2f(h1));
        BHL[pidx(kp, n)] = make_uint2((uint32_t)h0 | ((uint32_t)h1 << 16),
                                      (uint32_t)l0 | ((uint32_t)l1 << 16));
    }
    __syncthreads();   // only barrier: B ready

    const int w = tid >> 5, lane = tid & 31;
    const int grp = lane >> 2, kk = lane & 3;
    const int rowg = w >> 1;
    const int sh   = w & 1;

    float2* sb  = stage + w * 512;
    float*  sbf = reinterpret_cast<float*>(sb);
    const int rq  = lane >> 3, q = lane & 7;
    const int c2l = (2 * q) ^ ((rq & 3) << 2);
    const int swg = (grp & 3) << 2;

    for (int mt = by; mt < MTILES; mt += NYB) {
        // ---- a-fragments: 4 coalesced LDG.128 from prebuilt scratch ----
        const uint4* fp = reinterpret_cast<const uint4*>(
            ascr + ((size_t)(mt * 4 + rowg) * 32 + lane) * 16);
        uint2 fr[16];
        #pragma unroll
        for (int v = 0; v < 4; v++) {
            const uint4 t0 = fp[2 * v];
            const uint4 t1 = fp[2 * v + 1];
            fr[4 * v + 0] = make_uint2(t0.x, t0.y);
            fr[4 * v + 1] = make_uint2(t0.z, t0.w);
            fr[4 * v + 2] = make_uint2(t1.x, t1.y);
            fr[4 * v + 3] = make_uint2(t1.z, t1.w);
        }
        uint32_t ah[2][2][4], al[2][2][4];
        #pragma unroll
        for (int f = 0; f < 16; f++) {
            const int m = f >> 3, g = (f >> 2) & 1, i = f & 3;
            ah[m][g][i] = fr[f].x;
            al[m][g][i] = fr[f].y;
        }

        const int m0 = mt * MTB;
        float* Crow = C + (size_t)(m0 + rowg * 32) * CD + nb + sh * 64;

        #pragma unroll
        for (int half = 0; half < 2; half++) {
            #pragma unroll
            for (int spi = 0; spi < 4; spi++) {
                const int sp = half * 4 + spi;
                float acc[2][4];
                #pragma unroll
                for (int m = 0; m < 2; m++)
                    #pragma unroll
                    for (int t2 = 0; t2 < 4; t2++) acc[m][t2] = 0.f;

                const int nloc = sh * 64 + ((sp ^ kk) << 3) + grp;
                #pragma unroll
                for (int g = 0; g < 2; g++) {
                    const int p0 = g * 8 + kk;
                    const uint2 b0 = BHL[p0 * PSTR + nloc];
                    const uint2 b1 = BHL[(p0 + 4) * PSTR + nloc];
                    #pragma unroll
                    for (int m = 0; m < 2; m++) {
                        mma_bf16(acc[m], ah[m][g], b0.x, b1.x);
                        mma_bf16(acc[m], al[m][g], b0.x, b1.x);
                        mma_bf16(acc[m], ah[m][g], b0.y, b1.y);
                    }
                }

                const int c2s = (spi * 4 + kk) ^ swg;
                sb[(grp)      * 16 + c2s] = make_float2(acc[0][0], acc[0][1]);
                sb[(grp + 8)  * 16 + c2s] = make_float2(acc[0][2], acc[0][3]);
                sb[(grp + 16) * 16 + c2s] = make_float2(acc[1][0], acc[1][1]);
                sb[(grp + 24) * 16 + c2s] = make_float2(acc[1][2], acc[1][3]);
            }
            __syncwarp();

            float* Cst = Crow + half * 32 + q * 4;
            #pragma unroll
            for (int it = 0; it < 8; it++) {
                const int r = 4 * it + rq;
                const float4 v = *reinterpret_cast<const float4*>(sbf + r * 32 + c2l * 2);
                __stcs(reinterpret_cast<float4*>(Cst + (size_t)r * CD), v);
            }
            __syncwarp();
        }
    }
}

extern "C" void kernel_launch(void* const* d_in, const int* in_sizes, int n_in,
                              void* d_out, int out_size)
{
    const float* alpha = (const float*)d_in[0];   // [64,400,25]
    const float* mu    = (const float*)d_in[1];   // [25,80]
    const float* D     = (const float*)d_in[2];   // [25,80,80]
    const float* asc   = (const float*)d_in[3];   // [25]

    float* out = (float*)d_out;
    float* m_o = out;                 // [64,400,80]
    float* c_o = out + (BT * NC);     // [64,400,80,80]

    static int inited = 0;
    if (!inited) {
        cudaFuncSetAttribute(fused_kernel,
                             cudaFuncAttributeMaxDynamicSharedMemorySize, SMB);
        inited = 1;
    }

    prep_kernel<<<BT / 256, 256>>>(alpha, asc);
    fused_kernel<<<dim3(NXB + 2, NYB), THREADS, SMB>>>(alpha, mu, D, asc, m_o, c_o);
}

// round 16
// speedup vs baseline: 1.2263x; 1.2263x over previous
#include <cuda_runtime.h>
#include <cstdint>

#define NS 25
#define NC 80
#define CD 6400
#define BT 25600

#define MTB 128
#define NTB 128
#define THREADS 256
#define NXB 50
#define NYB 8
#define MTILES 200
#define NMB 16

#define PL 16
#define PSTR 132             // uint2 per A plane
#define PSTRB 136            // uint32 per B plane (== 8 mod 32: conflict-free)

// dynamic smem layout (bytes)
#define OFF_AHL 0                              // 16 * 132 * 8 = 16896
#define OFF_BH  16896                          // 16 * 136 * 4 = 8704
#define OFF_BL  25600                          // 8704
#define OFF_SC  34304                          // 13 float2
#define SMB     34432

__device__ __forceinline__ uint16_t f2bf(float v) {
    uint16_t r;
    asm("cvt.rn.bf16.f32 %0, %1;" : "=h"(r) : "f"(v));
    return r;
}
__device__ __forceinline__ float bf2f(uint16_t h) {
    return __uint_as_float((uint32_t)h << 16);
}
__device__ __forceinline__ void mma_bf16(float* acc, const uint32_t* a,
                                         uint32_t b0, uint32_t b1) {
    asm volatile(
        "mma.sync.aligned.m16n8k16.row.col.f32.bf16.bf16.f32 "
        "{%0,%1,%2,%3}, {%4,%5,%6,%7}, {%8,%9}, {%0,%1,%2,%3};"
        : "+f"(acc[0]), "+f"(acc[1]), "+f"(acc[2]), "+f"(acc[3])
        : "r"(a[0]), "r"(a[1]), "r"(a[2]), "r"(a[3]), "r"(b0), "r"(b1));
}
__device__ __forceinline__ int pidx(int plane, int x) {
    return plane * PSTR + (x ^ ((plane & 3) << 3));
}
// B permutation: col c (0..15 in-block) = 4Q + q + 2s  ->  8s + 2Q + q
__device__ __forceinline__ int bperm(int n) {
    const int c = n & 15;
    return (n & ~15) + (((c & 2) << 2) | ((c >> 2) << 1) | (c & 1));
}
__device__ __forceinline__ float softplus_f(float x) { return log1pf(expf(x)); }

// ---------------------------------------------------------------------------
__global__ __launch_bounds__(THREADS, 3)
void fused_kernel(const float* __restrict__ alpha,
                  const float* __restrict__ mu,
                  const float* __restrict__ D,
                  const float* __restrict__ asc,
                  float* __restrict__ m_out,
                  float* __restrict__ C)
{
    extern __shared__ char dsm[];
    const int tid = threadIdx.x;
    const int bx = blockIdx.x, by = blockIdx.y;

    if (bx >= NXB) {
        // =================== m path ===================
        float* mu_s = reinterpret_cast<float*>(dsm);
        float* a_s  = mu_s + 2048;
        float* sc   = a_s + 3232;

        if (tid < NS) sc[tid] = softplus_f(asc[tid]);
        for (int i = tid; i < NS * NC; i += THREADS) mu_s[i] = mu[i];
        __syncthreads();

        const int active = (tid < 160);
        const int c = tid % 80, h = tid / 80;
        float mur[NS];
        if (active) {
            #pragma unroll
            for (int j = 0; j < NS; j++) mur[j] = mu_s[j * NC + c];
        }

        const int mid = (bx - NXB) + 2 * by;
        for (int mt = mid; mt < MTILES; mt += NMB) {
            const int bt0 = mt * MTB;
            __syncthreads();
            const float* ap = alpha + (size_t)bt0 * NS;
            for (int i = tid; i < MTB * NS; i += THREADS) {
                const int j = i % NS;
                a_s[i] = ap[i] * sc[j];
            }
            __syncthreads();
            if (active) {
                #pragma unroll 4
                for (int rr = 0; rr < 64; rr++) {
                    const int r = h * 64 + rr;
                    float s = 0.f;
                    #pragma unroll
                    for (int j = 0; j < NS; j++) s = fmaf(a_s[r * NS + j], mur[j], s);
                    __stcs(&m_out[(size_t)(bt0 + r) * NC + c], s);
                }
            }
        }
        return;
    }

    // =================== C path ===================
    uint2*    AHL = reinterpret_cast<uint2*>(dsm + OFF_AHL);
    uint32_t* BH  = reinterpret_cast<uint32_t*>(dsm + OFF_BH);
    uint32_t* BL  = reinterpret_cast<uint32_t*>(dsm + OFF_BL);
    float2*   sc2 = reinterpret_cast<float2*>(dsm + OFF_SC);

    if (tid < 13) {
        const float s0 = softplus_f(asc[2 * tid]);
        const float s1 = (tid < 12) ? softplus_f(asc[2 * tid + 1]) : 0.f;
        sc2[tid] = make_float2(s0, s1);
    }
    // zero pad planes 13..15
    for (int i = tid; i < 3 * PSTR; i += THREADS)
        AHL[13 * PSTR + i] = make_uint2(0, 0);
    for (int i = tid; i < 3 * PSTRB; i += THREADS) {
        BH[13 * PSTRB + i] = 0;
        BL[13 * PSTRB + i] = 0;
    }

    const int nb = bx * NTB;

    // ---- B split (once): permuted uint32 hi/lo planes ----
    for (int it = tid; it < 13 * NTB; it += THREADS) {
        const int kp = it >> 7, n = it & 127;
        const float v0 = D[(size_t)(2 * kp) * CD + nb + n];
        const float v1 = (kp < 12) ? D[(size_t)(2 * kp + 1) * CD + nb + n] : 0.f;
        const uint16_t h0 = f2bf(v0), h1 = f2bf(v1);
        const uint16_t l0 = f2bf(v0 - bf2f(h0)), l1 = f2bf(v1 - bf2f(h1));
        const int idx = kp * PSTRB + bperm(n);
        BH[idx] = (uint32_t)h0 | ((uint32_t)h1 << 16);
        BL[idx] = (uint32_t)l0 | ((uint32_t)l1 << 16);
    }

    const int w = tid >> 5, lane = tid & 31;
    const int grp = lane >> 2, kk = lane & 3;
    const int rowg = w >> 1;
    const int sh   = w & 1;

    for (int mt = by; mt < MTILES; mt += NYB) {
        const int m0 = mt * MTB;

        __syncthreads();
        // ---- A split: pair-granular ----
        {
            const float* ap = alpha + (size_t)m0 * NS;
            for (int i = tid; i < MTB * 13; i += THREADS) {
                const int r = i / 13, kp = i - r * 13;
                const float2 s = sc2[kp];
                const float v0 = ap[r * NS + 2 * kp] * s.x;
                const float v1 = (kp < 12) ? ap[r * NS + 2 * kp + 1] * s.y : 0.f;
                const uint16_t h0 = f2bf(v0), h1 = f2bf(v1);
                const uint16_t l0 = f2bf(v0 - bf2f(h0)), l1 = f2bf(v1 - bf2f(h1));
                AHL[pidx(kp, r)] = make_uint2((uint32_t)h0 | ((uint32_t)h1 << 16),
                                              (uint32_t)l0 | ((uint32_t)l1 << 16));
            }
        }
        __syncthreads();

        // ---- a-fragments (hi+lo), register-resident ----
        uint32_t ah[2][2][4], al[2][2][4];
        {
            const int kkx = kk << 3;
            #pragma unroll
            for (int m = 0; m < 2; m++) {
                const int rb = rowg * 32 + m * 16 + grp;
                #pragma unroll
                for (int g = 0; g < 2; g++) {
                    const int p0 = g * 8 + kk;
                    uint2 t;
                    t = AHL[p0 * PSTR + ((rb)     ^ kkx)]; ah[m][g][0] = t.x; al[m][g][0] = t.y;
                    t = AHL[p0 * PSTR + ((rb + 8) ^ kkx)]; ah[m][g][1] = t.x; al[m][g][1] = t.y;
                    t = AHL[(p0 + 4) * PSTR + ((rb)     ^ kkx)]; ah[m][g][2] = t.x; al[m][g][2] = t.y;
                    t = AHL[(p0 + 4) * PSTR + ((rb + 8) ^ kkx)]; ah[m][g][3] = t.x; al[m][g][3] = t.y;
                }
            }
        }

        float* Cw = C + (size_t)(m0 + rowg * 32) * CD + nb + sh * 64 + kk * 4;
        const int cb0 = sh * 64 + grp;

        #pragma unroll
        for (int p = 0; p < 4; p++) {
            float acc[2][2][4];       // [variant][m][4]
            #pragma unroll
            for (int v = 0; v < 2; v++)
                #pragma unroll
                for (int m = 0; m < 2; m++)
                    #pragma unroll
                    for (int q = 0; q < 4; q++) acc[v][m][q] = 0.f;

            const int cb = cb0 + p * 16;
            #pragma unroll
            for (int g = 0; g < 2; g++) {
                const int pA = (g * 8 + kk) * PSTRB + cb;
                const int pB = pA + 4 * PSTRB;
                const uint32_t bhA0 = BH[pA],     bhA1 = BH[pB];
                const uint32_t blA0 = BL[pA],     blA1 = BL[pB];
                const uint32_t bhB0 = BH[pA + 8], bhB1 = BH[pB + 8];
                const uint32_t blB0 = BL[pA + 8], blB1 = BL[pB + 8];
                #pragma unroll
                for (int m = 0; m < 2; m++) {
                    mma_bf16(acc[0][m], ah[m][g], bhA0, bhA1);
                    mma_bf16(acc[0][m], al[m][g], bhA0, bhA1);
                    mma_bf16(acc[0][m], ah[m][g], blA0, blA1);
                    mma_bf16(acc[1][m], ah[m][g], bhB0, bhB1);
                    mma_bf16(acc[1][m], al[m][g], bhB0, bhB1);
                    mma_bf16(acc[1][m], ah[m][g], blB0, blB1);
                }
            }

            // direct stores: float4 of 4 consecutive true columns
            #pragma unroll
            for (int m = 0; m < 2; m++) {
                float* r0 = Cw + (size_t)(m * 16 + grp) * CD + p * 16;
                __stcs(reinterpret_cast<float4*>(r0),
                       make_float4(acc[0][m][0], acc[0][m][1],
                                   acc[1][m][0], acc[1][m][1]));
                __stcs(reinterpret_cast<float4*>(r0 + (size_t)8 * CD),
                       make_float4(acc[0][m][2], acc[0][m][3],
                                   acc[1][m][2], acc[1][m][3]));
            }
        }
    }
}

extern "C" void kernel_launch(void* const* d_in, const int* in_sizes, int n_in,
                              void* d_out, int out_size)
{
    const float* alpha = (const float*)d_in[0];   // [64,400,25]
    const float* mu    = (const float*)d_in[1];   // [25,80]
    const float* D     = (const float*)d_in[2];   // [25,80,80]
    const float* asc   = (const float*)d_in[3];   // [25]

    float* out = (float*)d_out;
    float* m_o = out;                 // [64,400,80]
    float* c_o = out + (BT * NC);     // [64,400,80,80]

    static int inited = 0;
    if (!inited) {
        cudaFuncSetAttribute(fused_kernel,
                             cudaFuncAttributeMaxDynamicSharedMemorySize, SMB);
        inited = 1;
    }

    fused_kernel<<<dim3(NXB + 2, NYB), THREADS, SMB>>>(alpha, mu, D, asc, m_o, c_o);
}